// round 1
// baseline (speedup 1.0000x reference)
#include <cuda_runtime.h>

// Problem dims (fixed by the dataset)
#define BB 8
#define CC 512
#define NN 4096
#define II 128
#define SS 64   // spatial side

// -------- scratch (allocation-free rule: __device__ globals) --------
__device__ float g_v[(size_t)BB * NN * CC];     // [b][n][o]    64 MB
__device__ float g_q[(size_t)BB * NN * II];     // [b][n][i]    16 MB
__device__ float g_k[(size_t)BB * NN * II];     // [b][m][i]    16 MB
__device__ float g_rel[(size_t)BB * NN * NN];   // [b][n][m]   512 MB
__device__ float g_y[(size_t)BB * NN * CC];     // [b][n][o]    64 MB
__device__ float g_u[(size_t)BB * CC * NN];     // [b][o][n]    64 MB
__device__ float g_mean[CC];
__device__ float g_rstd[CC];

// ---------------- generic tiled SGEMM: C[m][n] = sum_k a(m,k)*b(n,k) --------
// 128x128 tile, BK=16, 256 threads, 8x8 per thread.
#define TM 128
#define TN 128
#define TK 16

__global__ __launch_bounds__(256, 2)
void gemm_nt(const float* __restrict__ A, const float* __restrict__ B,
             float* __restrict__ C,
             int M, int N, int K,
             long a_sm, long a_sk,
             long b_sn, long b_sk,
             long c_sm,
             long a_batch, long b_batch, long c_batch,
             int div_dist)
{
    __shared__ float As[TK][TM + 4];
    __shared__ float Bs[TK][TN + 4];

    const int bz = blockIdx.z;
    A += (size_t)bz * a_batch;
    B += (size_t)bz * b_batch;
    C += (size_t)bz * c_batch;

    const int m0 = blockIdx.y * TM;
    const int n0 = blockIdx.x * TN;
    const int tid = threadIdx.x;
    const int tx = tid & 15;   // 0..15 -> 2 col chunks of 4
    const int ty = tid >> 4;   // 0..15 -> 2 row chunks of 4

    float acc[8][8];
#pragma unroll
    for (int i = 0; i < 8; i++)
#pragma unroll
        for (int j = 0; j < 8; j++) acc[i][j] = 0.f;

    for (int k0 = 0; k0 < K; k0 += TK) {
        // ---- load A tile ----
        if (a_sk == 1) {
#pragma unroll
            for (int i = 0; i < 2; i++) {
                int f = tid + i * 256;           // 0..511
                int mm = f >> 2;                 // 0..127
                int k4 = f & 3;                  // 0..3
                float4 vv = *(const float4*)(A + (size_t)(m0 + mm) * a_sm + (k0 + k4 * 4));
                As[k4 * 4 + 0][mm] = vv.x;
                As[k4 * 4 + 1][mm] = vv.y;
                As[k4 * 4 + 2][mm] = vv.z;
                As[k4 * 4 + 3][mm] = vv.w;
            }
        } else {
#pragma unroll
            for (int i = 0; i < 8; i++) {
                int e = tid + i * 256;           // 0..2047
                int kk = e >> 7;                 // 0..15
                int mm = e & 127;
                As[kk][mm] = A[(size_t)(m0 + mm) * a_sm + (size_t)(k0 + kk) * a_sk];
            }
        }
        // ---- load B tile ----
        if (b_sk == 1) {
#pragma unroll
            for (int i = 0; i < 2; i++) {
                int f = tid + i * 256;
                int nn = f >> 2;
                int k4 = f & 3;
                float4 vv = *(const float4*)(B + (size_t)(n0 + nn) * b_sn + (k0 + k4 * 4));
                Bs[k4 * 4 + 0][nn] = vv.x;
                Bs[k4 * 4 + 1][nn] = vv.y;
                Bs[k4 * 4 + 2][nn] = vv.z;
                Bs[k4 * 4 + 3][nn] = vv.w;
            }
        } else {
#pragma unroll
            for (int i = 0; i < 8; i++) {
                int e = tid + i * 256;
                int kk = e >> 7;
                int nn = e & 127;
                Bs[kk][nn] = B[(size_t)(n0 + nn) * b_sn + (size_t)(k0 + kk) * b_sk];
            }
        }
        __syncthreads();

#pragma unroll
        for (int kk = 0; kk < TK; kk++) {
            float a[8], b[8];
            *(float4*)&a[0] = *(const float4*)&As[kk][ty * 4];
            *(float4*)&a[4] = *(const float4*)&As[kk][64 + ty * 4];
            *(float4*)&b[0] = *(const float4*)&Bs[kk][tx * 4];
            *(float4*)&b[4] = *(const float4*)&Bs[kk][64 + tx * 4];
#pragma unroll
            for (int i = 0; i < 8; i++)
#pragma unroll
                for (int j = 0; j < 8; j++)
                    acc[i][j] += a[i] * b[j];
        }
        __syncthreads();
    }

    // ---- epilogue ----
#pragma unroll
    for (int i = 0; i < 8; i++) {
        int gm = m0 + ((i < 4) ? (ty * 4 + i) : (64 + ty * 4 + (i - 4)));
#pragma unroll
        for (int jc = 0; jc < 2; jc++) {
            int gn = n0 + jc * 64 + tx * 4;
            float4 vv;
            float* vp = &vv.x;
#pragma unroll
            for (int j = 0; j < 4; j++) {
                float val = acc[i][jc * 4 + j];
                if (div_dist) {
                    int gnn = gn + j;
                    int di = (gm >> 6) - (gnn >> 6);
                    int dj = (gm & 63) - (gnn & 63);
                    val /= (sqrtf((float)(di * di + dj * dj)) + 1.0f);
                }
                vp[j] = val;
            }
            *(float4*)(C + (size_t)gm * c_sm + gn) = vv;
        }
    }
}

// ---------------- row softmax over g_rel rows (4096 wide) -------------------
__global__ void softmax_kernel(float* __restrict__ rel)
{
    __shared__ float red1[8];
    __shared__ float red2[8];
    const size_t row = blockIdx.x;
    float4* p = (float4*)(rel + row * (size_t)NN);
    const int tid = threadIdx.x; // 256

    float4 v[4];
    float mx = -3.0e38f;
#pragma unroll
    for (int i = 0; i < 4; i++) {
        v[i] = p[tid + i * 256];
        mx = fmaxf(mx, fmaxf(fmaxf(v[i].x, v[i].y), fmaxf(v[i].z, v[i].w)));
    }
#pragma unroll
    for (int o = 16; o > 0; o >>= 1)
        mx = fmaxf(mx, __shfl_xor_sync(0xffffffffu, mx, o));
    if ((tid & 31) == 0) red1[tid >> 5] = mx;
    __syncthreads();
    mx = red1[0];
#pragma unroll
    for (int w = 1; w < 8; w++) mx = fmaxf(mx, red1[w]);

    float s = 0.f;
#pragma unroll
    for (int i = 0; i < 4; i++) {
        v[i].x = __expf(v[i].x - mx);
        v[i].y = __expf(v[i].y - mx);
        v[i].z = __expf(v[i].z - mx);
        v[i].w = __expf(v[i].w - mx);
        s += v[i].x + v[i].y + v[i].z + v[i].w;
    }
#pragma unroll
    for (int o = 16; o > 0; o >>= 1)
        s += __shfl_xor_sync(0xffffffffu, s, o);
    if ((tid & 31) == 0) red2[tid >> 5] = s;
    __syncthreads();
    s = 0.f;
#pragma unroll
    for (int w = 0; w < 8; w++) s += red2[w];
    float inv = 1.0f / s;
#pragma unroll
    for (int i = 0; i < 4; i++) {
        v[i].x *= inv; v[i].y *= inv; v[i].z *= inv; v[i].w *= inv;
        p[tid + i * 256] = v[i];
    }
}

// ---------------- BN statistics: one block per channel ----------------------
__global__ void bn_stats(const float* __restrict__ u)
{
    __shared__ float rs[8], rs2[8];
    const int c = blockIdx.x;
    const int tid = threadIdx.x; // 256
    float s = 0.f, s2 = 0.f;
    for (int b = 0; b < BB; b++) {
        const float* up = u + ((size_t)b * CC + c) * NN;
        for (int n = tid; n < NN; n += 256) {
            float t = up[n];
            s += t;
            s2 += t * t;
        }
    }
#pragma unroll
    for (int o = 16; o > 0; o >>= 1) {
        s  += __shfl_xor_sync(0xffffffffu, s, o);
        s2 += __shfl_xor_sync(0xffffffffu, s2, o);
    }
    if ((tid & 31) == 0) { rs[tid >> 5] = s; rs2[tid >> 5] = s2; }
    __syncthreads();
    if (tid == 0) {
        float S = 0.f, S2 = 0.f;
#pragma unroll
        for (int w = 0; w < 8; w++) { S += rs[w]; S2 += rs2[w]; }
        const float cnt = (float)(BB * NN);
        float mean = S / cnt;
        float var = S2 / cnt - mean * mean;
        g_mean[c] = mean;
        g_rstd[c] = rsqrtf(var + 1e-5f);
    }
}

// ---------------- BN apply + residual + relu --------------------------------
__global__ void bn_relu_kernel(const float* __restrict__ u,
                               const float* __restrict__ x,
                               const float* __restrict__ gamma,
                               const float* __restrict__ beta,
                               float* __restrict__ out)
{
    size_t i4 = (size_t)blockIdx.x * blockDim.x + threadIdx.x; // float4 index
    int c = (int)((i4 * 4 / NN) % CC);
    float m = g_mean[c];
    float r = g_rstd[c] * gamma[c];
    float bt = beta[c];
    float4 uu = ((const float4*)u)[i4];
    float4 xx = ((const float4*)x)[i4];
    float4 o;
    o.x = fmaxf((uu.x - m) * r + bt + xx.x, 0.f);
    o.y = fmaxf((uu.y - m) * r + bt + xx.y, 0.f);
    o.z = fmaxf((uu.z - m) * r + bt + xx.z, 0.f);
    o.w = fmaxf((uu.w - m) * r + bt + xx.w, 0.f);
    ((float4*)out)[i4] = o;
}

// ---------------- launch ----------------------------------------------------
extern "C" void kernel_launch(void* const* d_in, const int* in_sizes, int n_in,
                              void* d_out, int out_size)
{
    const float* x     = (const float*)d_in[0];
    const float* Wv    = (const float*)d_in[1];
    const float* Wq    = (const float*)d_in[2];
    const float* Wk    = (const float*)d_in[3];
    const float* Wu    = (const float*)d_in[4];
    const float* gamma = (const float*)d_in[5];
    const float* beta  = (const float*)d_in[6];
    float* out = (float*)d_out;

    float *v, *q, *k, *rel, *y, *u;
    cudaGetSymbolAddress((void**)&v,   g_v);
    cudaGetSymbolAddress((void**)&q,   g_q);
    cudaGetSymbolAddress((void**)&k,   g_k);
    cudaGetSymbolAddress((void**)&rel, g_rel);
    cudaGetSymbolAddress((void**)&y,   g_y);
    cudaGetSymbolAddress((void**)&u,   g_u);

    dim3 thr(256);

    // v[b][n][o] = sum_c Wv[o][c] * x[b][c][n]
    gemm_nt<<<dim3(CC / TN, NN / TM, BB), thr>>>(
        x, Wv, v, NN, CC, CC,
        1L, (long)NN,            // a: x^T  (m=n token, k=c)
        (long)CC, 1L,            // b: Wv   (n=o, k=c)
        (long)CC,
        (long)CC * NN, 0L, (long)NN * CC, 0);

    // q[b][n][i]
    gemm_nt<<<dim3(II / TN, NN / TM, BB), thr>>>(
        x, Wq, q, NN, II, CC,
        1L, (long)NN,
        (long)CC, 1L,
        (long)II,
        (long)CC * NN, 0L, (long)NN * II, 0);

    // k stored transposed: k[b][m][i]
    gemm_nt<<<dim3(II / TN, NN / TM, BB), thr>>>(
        x, Wk, k, NN, II, CC,
        1L, (long)NN,
        (long)CC, 1L,
        (long)II,
        (long)CC * NN, 0L, (long)NN * II, 0);

    // rel[b][n][m] = (q[n]·k[m]) / dist(n,m)
    gemm_nt<<<dim3(NN / TN, NN / TM, BB), thr>>>(
        q, k, rel, NN, NN, II,
        (long)II, 1L,
        (long)II, 1L,
        (long)NN,
        (long)NN * II, (long)NN * II, (long)NN * NN, 1);

    // softmax rows
    softmax_kernel<<<BB * NN, 256>>>(rel);

    // y[b][n][o] = sum_m rel[n][m] * v[m][o]
    gemm_nt<<<dim3(CC / TN, NN / TM, BB), thr>>>(
        rel, v, y, NN, CC, NN,
        (long)NN, 1L,
        1L, (long)CC,
        (long)CC,
        (long)NN * NN, (long)NN * CC, (long)NN * CC, 0);

    // u[b][o][n] = sum_c Wu[o][c] * y[b][n][c]
    gemm_nt<<<dim3(NN / TN, CC / TM, BB), thr>>>(
        Wu, y, u, CC, NN, CC,
        (long)CC, 1L,
        (long)CC, 1L,
        (long)NN,
        0L, (long)NN * CC, (long)CC * NN, 0);

    // BN stats + apply + residual + relu
    bn_stats<<<CC, 256>>>(u);
    bn_relu_kernel<<<(BB * CC * (size_t)NN / 4) / 256, 256>>>(u, x, gamma, beta, out);
}

// round 3
// speedup vs baseline: 2.4163x; 2.4163x over previous
#include <cuda_runtime.h>
#include <cuda_bf16.h>
#include <stdint.h>

#define BB 8
#define CC 512
#define NN 4096
#define II 128

// ---------------- scratch (__device__ globals; no allocation allowed) -------
__device__ __nv_bfloat16 g_xs_h[(size_t)BB * NN * CC];
__device__ __nv_bfloat16 g_xs_l[(size_t)BB * NN * CC];
__device__ __nv_bfloat16 g_wv_h[CC * CC], g_wv_l[CC * CC];
__device__ __nv_bfloat16 g_wq_h[II * CC], g_wq_l[II * CC];
__device__ __nv_bfloat16 g_wk_h[II * CC], g_wk_l[II * CC];
__device__ __nv_bfloat16 g_wu_h[CC * CC], g_wu_l[CC * CC];
__device__ __nv_bfloat16 g_q_h[(size_t)BB * NN * II], g_q_l[(size_t)BB * NN * II];
__device__ __nv_bfloat16 g_k_h[(size_t)BB * NN * II], g_k_l[(size_t)BB * NN * II];
__device__ __nv_bfloat16 g_vT_h[(size_t)BB * CC * NN], g_vT_l[(size_t)BB * CC * NN];
__device__ float         g_rel[(size_t)BB * NN * NN];
__device__ __nv_bfloat16 g_P_h[(size_t)BB * NN * NN], g_P_l[(size_t)BB * NN * NN];
__device__ __nv_bfloat16 g_y_h[(size_t)BB * NN * CC], g_y_l[(size_t)BB * NN * CC];
__device__ float         g_u[(size_t)BB * CC * NN];
__device__ float g_mean[CC], g_rstd[CC];
__device__ float g_rdist[8192];   // 1/(sqrt(d2)+1), d2 <= 2*63^2

// ---------------- PTX helpers (all portable, non-'a' features) --------------
__device__ __forceinline__ uint32_t s2u(const void* p) {
    uint32_t a;
    asm("{ .reg .u64 t; cvta.to.shared.u64 t, %1; cvt.u32.u64 %0, t; }" : "=r"(a) : "l"(p));
    return a;
}
__device__ __forceinline__ void cpa16(uint32_t s, const void* g) {
    asm volatile("cp.async.cg.shared.global [%0], [%1], 16;" :: "r"(s), "l"(g) : "memory");
}
__device__ __forceinline__ void cpa_commit() { asm volatile("cp.async.commit_group;" ::: "memory"); }
template <int W> __device__ __forceinline__ void cpa_wait() {
    asm volatile("cp.async.wait_group %0;" :: "n"(W) : "memory");
}
__device__ __forceinline__ void ldsm4(uint32_t* r, uint32_t addr) {
    asm volatile("ldmatrix.sync.aligned.m8n8.x4.shared.b16 {%0,%1,%2,%3}, [%4];"
                 : "=r"(r[0]), "=r"(r[1]), "=r"(r[2]), "=r"(r[3]) : "r"(addr));
}
__device__ __forceinline__ void mma_bf16(float* d, const uint32_t* a, const uint32_t* b) {
    asm volatile(
        "mma.sync.aligned.m16n8k16.row.col.f32.bf16.bf16.f32 "
        "{%0,%1,%2,%3}, {%4,%5,%6,%7}, {%8,%9}, {%0,%1,%2,%3};"
        : "+f"(d[0]), "+f"(d[1]), "+f"(d[2]), "+f"(d[3])
        : "r"(a[0]), "r"(a[1]), "r"(a[2]), "r"(a[3]), "r"(b[0]), "r"(b[1]));
}
__device__ __forceinline__ void split_pk(float a, float b, uint32_t& hi, uint32_t& lo) {
    __nv_bfloat162 h, l;
    h.x = __float2bfloat16(a); h.y = __float2bfloat16(b);
    l.x = __float2bfloat16(a - __bfloat162float(h.x));
    l.y = __float2bfloat16(b - __bfloat162float(h.y));
    hi = *reinterpret_cast<uint32_t*>(&h);
    lo = *reinterpret_cast<uint32_t*>(&l);
}

// ---------------- split-bf16 HMMA GEMM ---------------------------------------
// C[M,N] = A[M,K] * B[N,K]^T ; A,B given as (hi,lo) bf16 pairs, K-major, ld==K.
// CTA tile 128x128, K-chunk 32, 8 warps (4m x 2n), warp tile 32x64.
// modes: 0 = fp32 out, 1 = fp32 * (1/dist) out, 2 = bf16 (hi,lo) pair out.
#define ROWB 80                    // padded row stride bytes (32 bf16 -> 80B)
#define ARR (128 * ROWB)           // one operand array per stage
#define STG (4 * ARR)              // Ah, Al, Bh, Bl

__global__ void __launch_bounds__(256, 1)
gemm_mma(const __nv_bfloat16* __restrict__ Ah_, const __nv_bfloat16* __restrict__ Al_,
         const __nv_bfloat16* __restrict__ Bh_, const __nv_bfloat16* __restrict__ Bl_,
         int K, long a_batch, long b_batch,
         float* __restrict__ Cf,
         __nv_bfloat16* __restrict__ Chi, __nv_bfloat16* __restrict__ Clo,
         long c_batch, int Nld, int mode)
{
    extern __shared__ char smem[];
    const uint32_t sb = s2u(smem);
    const int tid = threadIdx.x;
    const int wid = tid >> 5;
    const int lane = tid & 31;
    const int bz = blockIdx.z;
    const int m0 = blockIdx.y * 128;
    const int n0 = blockIdx.x * 128;
    const int warp_m = wid >> 1;     // 0..3
    const int warp_n = wid & 1;      // 0..1

    const __nv_bfloat16* Ah = Ah_ + (size_t)bz * a_batch + (size_t)m0 * K;
    const __nv_bfloat16* Al = Al_ + (size_t)bz * a_batch + (size_t)m0 * K;
    const __nv_bfloat16* Bh = Bh_ + (size_t)bz * b_batch + (size_t)n0 * K;
    const __nv_bfloat16* Bl = Bl_ + (size_t)bz * b_batch + (size_t)n0 * K;

    const int nch = K >> 5;

    auto load_chunk = [&](int ci, int stg) {
        const uint32_t st = sb + stg * STG;
        const size_t k0 = (size_t)ci * 32;
#pragma unroll
        for (int p = 0; p < 2; p++) {
            int e = tid + p * 256;         // 0..511
            int r = e >> 2, sgs = e & 3;
            uint32_t so = (uint32_t)r * ROWB + sgs * 16;
            size_t go = (size_t)r * K + k0 + sgs * 8;
            cpa16(st +           so, Ah + go);
            cpa16(st + ARR +     so, Al + go);
            cpa16(st + 2 * ARR + so, Bh + go);
            cpa16(st + 3 * ARR + so, Bl + go);
        }
        cpa_commit();
    };

    load_chunk(0, 0);
    if (nch > 1) load_chunk(1, 1);

    // lane offsets for ldmatrix (bytes)
    const int lt = lane & 7, ltile = lane >> 3;
    const uint32_t aLane = (uint32_t)(lt + ((ltile & 1) << 3)) * ROWB + ((ltile >> 1) << 4);
    const uint32_t bLane = (uint32_t)(lt + ((ltile >> 1) << 3)) * ROWB + ((ltile & 1) << 4);

    float acc[2][8][4];
#pragma unroll
    for (int i = 0; i < 2; i++)
#pragma unroll
        for (int j = 0; j < 8; j++)
#pragma unroll
            for (int c = 0; c < 4; c++) acc[i][j][c] = 0.f;

    for (int i = 0; i < nch; i++) {
        const int b = i & 1;
        const uint32_t st = sb + b * STG;
        if (i + 1 < nch) cpa_wait<1>(); else cpa_wait<0>();
        __syncthreads();

        const uint32_t aBh = st +           (uint32_t)warp_m * 32 * ROWB + aLane;
        const uint32_t aBl = st + ARR +     (uint32_t)warp_m * 32 * ROWB + aLane;
        const uint32_t bBh = st + 2 * ARR + (uint32_t)warp_n * 64 * ROWB + bLane;
        const uint32_t bBl = st + 3 * ARR + (uint32_t)warp_n * 64 * ROWB + bLane;

#pragma unroll
        for (int ks = 0; ks < 2; ks++) {
            uint32_t aH[2][4], aL[2][4], bH[4][4], bL[4][4];
#pragma unroll
            for (int mt = 0; mt < 2; mt++) {
                ldsm4(aH[mt], aBh + mt * 16 * ROWB + ks * 32);
                ldsm4(aL[mt], aBl + mt * 16 * ROWB + ks * 32);
            }
#pragma unroll
            for (int np = 0; np < 4; np++) {   // each covers 2 n-tiles
                ldsm4(bH[np], bBh + np * 16 * ROWB + ks * 32);
                ldsm4(bL[np], bBl + np * 16 * ROWB + ks * 32);
            }
#pragma unroll
            for (int mt = 0; mt < 2; mt++)
#pragma unroll
                for (int nt = 0; nt < 8; nt++) {
                    const uint32_t* bh = &bH[nt >> 1][(nt & 1) * 2];
                    const uint32_t* bl = &bL[nt >> 1][(nt & 1) * 2];
                    mma_bf16(acc[mt][nt], aH[mt], bh);
                    mma_bf16(acc[mt][nt], aH[mt], bl);
                    mma_bf16(acc[mt][nt], aL[mt], bh);
                }
        }
        __syncthreads();
        if (i + 2 < nch) load_chunk(i + 2, b);
    }

    // ---- epilogue ----
    const int gp = lane >> 2, tq = lane & 3;
    const int mbase = m0 + warp_m * 32;
    const int nbase = n0 + warp_n * 64;

#pragma unroll
    for (int mt = 0; mt < 2; mt++) {
#pragma unroll
        for (int half = 0; half < 2; half++) {
            const int r = mbase + mt * 16 + half * 8 + gp;
            if (mode == 2) {
                __nv_bfloat16* oh = Chi + (size_t)bz * c_batch + (size_t)r * Nld;
                __nv_bfloat16* ol = Clo + (size_t)bz * c_batch + (size_t)r * Nld;
#pragma unroll
                for (int nt = 0; nt < 8; nt++) {
                    const int col = nbase + nt * 8 + 2 * tq;
                    uint32_t hi, lo;
                    split_pk(acc[mt][nt][half * 2], acc[mt][nt][half * 2 + 1], hi, lo);
                    *(uint32_t*)(oh + col) = hi;
                    *(uint32_t*)(ol + col) = lo;
                }
            } else {
                float* oc = Cf + (size_t)bz * c_batch + (size_t)r * Nld;
                if (mode == 1) {
                    const int ri = r >> 6, rj = r & 63;
#pragma unroll
                    for (int nt = 0; nt < 8; nt++) {
                        const int col = nbase + nt * 8 + 2 * tq;
                        int di0 = ri - (col >> 6);
                        float2 o;
                        int j0 = rj - (col & 63);
                        int j1 = rj - ((col + 1) & 63);
                        int dd0 = (col & 63) == 63 ? 0 : 0; (void)dd0;
                        // col and col+1 are in the same 64-row unless col&63==63 (never: col even)
                        o.x = acc[mt][nt][half * 2]     * g_rdist[di0 * di0 + j0 * j0];
                        o.y = acc[mt][nt][half * 2 + 1] * g_rdist[di0 * di0 + j1 * j1];
                        *(float2*)(oc + col) = o;
                    }
                } else {
#pragma unroll
                    for (int nt = 0; nt < 8; nt++) {
                        const int col = nbase + nt * 8 + 2 * tq;
                        float2 o;
                        o.x = acc[mt][nt][half * 2];
                        o.y = acc[mt][nt][half * 2 + 1];
                        *(float2*)(oc + col) = o;
                    }
                }
            }
        }
    }
}

// ---------------- prep kernels ----------------------------------------------
__global__ void init_rdist() {
    int i = blockIdx.x * 256 + threadIdx.x;
    if (i < 8192) g_rdist[i] = 1.0f / (sqrtf((float)i) + 1.0f);
}

__global__ void split_w(const float* __restrict__ w, __nv_bfloat16* __restrict__ h,
                        __nv_bfloat16* __restrict__ l, int n) {
    int i = blockIdx.x * 256 + threadIdx.x;
    if (i < n) {
        float v = w[i];
        __nv_bfloat16 hh = __float2bfloat16(v);
        h[i] = hh;
        l[i] = __float2bfloat16(v - __bfloat162float(hh));
    }
}

// x[b][c][n] -> xs[b][n][c] as bf16 hi/lo
__global__ void split_transpose(const float* __restrict__ x) {
    __shared__ float t[32][33];
    const int b = blockIdx.z;
    const int n0 = blockIdx.x << 5, c0 = blockIdx.y << 5;
    const int tx = threadIdx.x, ty = threadIdx.y;
    const float* xp = x + ((size_t)b * CC + c0) * NN + n0;
#pragma unroll
    for (int i = 0; i < 4; i++) t[ty + i * 8][tx] = xp[(size_t)(ty + i * 8) * NN + tx];
    __syncthreads();
    const size_t ob = ((size_t)b * NN + n0) * CC + c0;
#pragma unroll
    for (int i = 0; i < 4; i++) {
        float v = t[tx][ty + i * 8];
        __nv_bfloat16 h = __float2bfloat16(v);
        size_t o = ob + (size_t)(ty + i * 8) * CC + tx;
        g_xs_h[o] = h;
        g_xs_l[o] = __float2bfloat16(v - __bfloat162float(h));
    }
}

// row softmax, fp32 in -> bf16 pair out
__global__ void softmax_bf16(const float* __restrict__ rel) {
    __shared__ float red1[8], red2[8];
    const size_t row = blockIdx.x;
    const float4* p = (const float4*)(rel + row * (size_t)NN);
    const int tid = threadIdx.x;

    float4 v[4];
    float mx = -3.0e38f;
#pragma unroll
    for (int i = 0; i < 4; i++) {
        v[i] = p[tid + i * 256];
        mx = fmaxf(mx, fmaxf(fmaxf(v[i].x, v[i].y), fmaxf(v[i].z, v[i].w)));
    }
#pragma unroll
    for (int o = 16; o > 0; o >>= 1) mx = fmaxf(mx, __shfl_xor_sync(0xffffffffu, mx, o));
    if ((tid & 31) == 0) red1[tid >> 5] = mx;
    __syncthreads();
    mx = red1[0];
#pragma unroll
    for (int w = 1; w < 8; w++) mx = fmaxf(mx, red1[w]);

    float s = 0.f;
#pragma unroll
    for (int i = 0; i < 4; i++) {
        v[i].x = __expf(v[i].x - mx); v[i].y = __expf(v[i].y - mx);
        v[i].z = __expf(v[i].z - mx); v[i].w = __expf(v[i].w - mx);
        s += v[i].x + v[i].y + v[i].z + v[i].w;
    }
#pragma unroll
    for (int o = 16; o > 0; o >>= 1) s += __shfl_xor_sync(0xffffffffu, s, o);
    if ((tid & 31) == 0) red2[tid >> 5] = s;
    __syncthreads();
    s = 0.f;
#pragma unroll
    for (int w = 0; w < 8; w++) s += red2[w];
    const float inv = 1.0f / s;

    uint2* H = (uint2*)(g_P_h + row * (size_t)NN);
    uint2* L = (uint2*)(g_P_l + row * (size_t)NN);
#pragma unroll
    for (int i = 0; i < 4; i++) {
        float f0 = v[i].x * inv, f1 = v[i].y * inv, f2 = v[i].z * inv, f3 = v[i].w * inv;
        uint2 hh, ll;
        split_pk(f0, f1, hh.x, ll.x);
        split_pk(f2, f3, hh.y, ll.y);
        H[tid + i * 256] = hh;
        L[tid + i * 256] = ll;
    }
}

// ---------------- BN ---------------------------------------------------------
__global__ void bn_stats(const float* __restrict__ u) {
    __shared__ float rs[8], rs2[8];
    const int c = blockIdx.x;
    const int tid = threadIdx.x;
    float s = 0.f, s2 = 0.f;
    for (int b = 0; b < BB; b++) {
        const float* up = u + ((size_t)b * CC + c) * NN;
        for (int n = tid; n < NN; n += 256) {
            float t = up[n];
            s += t; s2 += t * t;
        }
    }
#pragma unroll
    for (int o = 16; o > 0; o >>= 1) {
        s  += __shfl_xor_sync(0xffffffffu, s, o);
        s2 += __shfl_xor_sync(0xffffffffu, s2, o);
    }
    if ((tid & 31) == 0) { rs[tid >> 5] = s; rs2[tid >> 5] = s2; }
    __syncthreads();
    if (tid == 0) {
        float S = 0.f, S2 = 0.f;
#pragma unroll
        for (int w = 0; w < 8; w++) { S += rs[w]; S2 += rs2[w]; }
        const float cnt = (float)(BB * NN);
        float mean = S / cnt;
        float var = S2 / cnt - mean * mean;
        g_mean[c] = mean;
        g_rstd[c] = rsqrtf(var + 1e-5f);
    }
}

__global__ void bn_relu_kernel(const float* __restrict__ u, const float* __restrict__ x,
                               const float* __restrict__ gamma, const float* __restrict__ beta,
                               float* __restrict__ out) {
    size_t i4 = (size_t)blockIdx.x * blockDim.x + threadIdx.x;
    int c = (int)((i4 * 4 / NN) % CC);
    float m = g_mean[c];
    float r = g_rstd[c] * gamma[c];
    float bt = beta[c];
    float4 uu = ((const float4*)u)[i4];
    float4 xx = ((const float4*)x)[i4];
    float4 o;
    o.x = fmaxf((uu.x - m) * r + bt + xx.x, 0.f);
    o.y = fmaxf((uu.y - m) * r + bt + xx.y, 0.f);
    o.z = fmaxf((uu.z - m) * r + bt + xx.z, 0.f);
    o.w = fmaxf((uu.w - m) * r + bt + xx.w, 0.f);
    ((float4*)out)[i4] = o;
}

// ---------------- launch ------------------------------------------------------
extern "C" void kernel_launch(void* const* d_in, const int* in_sizes, int n_in,
                              void* d_out, int out_size)
{
    const float* x     = (const float*)d_in[0];
    const float* Wv    = (const float*)d_in[1];
    const float* Wq    = (const float*)d_in[2];
    const float* Wk    = (const float*)d_in[3];
    const float* Wu    = (const float*)d_in[4];
    const float* gamma = (const float*)d_in[5];
    const float* beta  = (const float*)d_in[6];
    float* out = (float*)d_out;

    __nv_bfloat16 *xs_h, *xs_l, *wv_h, *wv_l, *wq_h, *wq_l, *wk_h, *wk_l, *wu_h, *wu_l;
    __nv_bfloat16 *q_h, *q_l, *k_h, *k_l, *vT_h, *vT_l, *P_h, *P_l, *y_h, *y_l;
    float *rel, *u;
    cudaGetSymbolAddress((void**)&xs_h, g_xs_h); cudaGetSymbolAddress((void**)&xs_l, g_xs_l);
    cudaGetSymbolAddress((void**)&wv_h, g_wv_h); cudaGetSymbolAddress((void**)&wv_l, g_wv_l);
    cudaGetSymbolAddress((void**)&wq_h, g_wq_h); cudaGetSymbolAddress((void**)&wq_l, g_wq_l);
    cudaGetSymbolAddress((void**)&wk_h, g_wk_h); cudaGetSymbolAddress((void**)&wk_l, g_wk_l);
    cudaGetSymbolAddress((void**)&wu_h, g_wu_h); cudaGetSymbolAddress((void**)&wu_l, g_wu_l);
    cudaGetSymbolAddress((void**)&q_h,  g_q_h);  cudaGetSymbolAddress((void**)&q_l,  g_q_l);
    cudaGetSymbolAddress((void**)&k_h,  g_k_h);  cudaGetSymbolAddress((void**)&k_l,  g_k_l);
    cudaGetSymbolAddress((void**)&vT_h, g_vT_h); cudaGetSymbolAddress((void**)&vT_l, g_vT_l);
    cudaGetSymbolAddress((void**)&P_h,  g_P_h);  cudaGetSymbolAddress((void**)&P_l,  g_P_l);
    cudaGetSymbolAddress((void**)&y_h,  g_y_h);  cudaGetSymbolAddress((void**)&y_l,  g_y_l);
    cudaGetSymbolAddress((void**)&rel,  g_rel);
    cudaGetSymbolAddress((void**)&u,    g_u);

    const int SMEM = 2 * STG;   // 81920 bytes
    cudaFuncSetAttribute(gemm_mma, cudaFuncAttributeMaxDynamicSharedMemorySize, SMEM);

    // prep
    init_rdist<<<32, 256>>>();
    split_w<<<(CC * CC + 255) / 256, 256>>>(Wv, wv_h, wv_l, CC * CC);
    split_w<<<(II * CC + 255) / 256, 256>>>(Wq, wq_h, wq_l, II * CC);
    split_w<<<(II * CC + 255) / 256, 256>>>(Wk, wk_h, wk_l, II * CC);
    split_w<<<(CC * CC + 255) / 256, 256>>>(Wu, wu_h, wu_l, CC * CC);
    split_transpose<<<dim3(NN / 32, CC / 32, BB), dim3(32, 8)>>>(x);

    // q[b][n][i] = xT[n][:] . Wq[i][:]      M=NN, N=II, K=CC
    gemm_mma<<<dim3(1, 32, BB), 256, SMEM>>>(
        xs_h, xs_l, wq_h, wq_l, CC, (long)NN * CC, 0L,
        nullptr, q_h, q_l, (long)NN * II, II, 2);
    // k[b][m][i]
    gemm_mma<<<dim3(1, 32, BB), 256, SMEM>>>(
        xs_h, xs_l, wk_h, wk_l, CC, (long)NN * CC, 0L,
        nullptr, k_h, k_l, (long)NN * II, II, 2);
    // vT[b][o][m] = Wv[o][:] . xT[m][:]     M=CC, N=NN, K=CC
    gemm_mma<<<dim3(32, 4, BB), 256, SMEM>>>(
        wv_h, wv_l, xs_h, xs_l, CC, 0L, (long)NN * CC,
        nullptr, vT_h, vT_l, (long)CC * NN, NN, 2);
    // rel[b][n][m] = (q[n].k[m]) / dist     M=NN, N=NN, K=II
    gemm_mma<<<dim3(32, 32, BB), 256, SMEM>>>(
        q_h, q_l, k_h, k_l, II, (long)NN * II, (long)NN * II,
        rel, nullptr, nullptr, (long)NN * NN, NN, 1);
    // softmax rows -> P (bf16 pair)
    softmax_bf16<<<BB * NN, 256>>>(rel);
    // y[b][n][o] = P[n][:] . vT[o][:]       M=NN, N=CC, K=NN
    gemm_mma<<<dim3(4, 32, BB), 256, SMEM>>>(
        P_h, P_l, vT_h, vT_l, NN, (long)NN * NN, (long)CC * NN,
        nullptr, y_h, y_l, (long)NN * CC, CC, 2);
    // u[b][o][n] = Wu[o][:] . y[n][:]       M=CC, N=NN, K=CC
    gemm_mma<<<dim3(32, 4, BB), 256, SMEM>>>(
        wu_h, wu_l, y_h, y_l, CC, 0L, (long)NN * CC,
        u, nullptr, nullptr, (long)CC * NN, NN, 0);

    bn_stats<<<CC, 256>>>(u);
    bn_relu_kernel<<<(int)(((size_t)BB * CC * NN / 4) / 256), 256>>>(u, x, gamma, beta, out);
}